// round 11
// baseline (speedup 1.0000x reference)
#include <cuda_runtime.h>
#include <cuda_bf16.h>
#include <cstdint>

// ---------------- problem constants ----------------
#define BSZ        4
#define DIM        512
#define D_INNER    1024
#define HEADDIM    128
#define NHEADS     8
#define D_STATE    128
#define D_CONV     4
#define CONV_DIM   1280          // D_INNER + 2*D_STATE
#define D_IN_PROJ  2312          // 2*D_INNER + 2*D_STATE + NHEADS
#define LSEQ       4096          // 16*16*16
#define NBL        (BSZ * LSEQ)  // 16384 rows (b,l)
#define TCH        64            // SSD chunk length
#define NCH        (LSEQ / TCH)  // 64 chunks per (b)

// ---------------- device scratch (static globals; no allocation) ----------------
__device__ __align__(128) float  g_zx  [(size_t)NBL * D_IN_PROJ];   // in_proj out (z | xBC)
__device__ __align__(128) float  g_conv[(size_t)NBL * CONV_DIM];    // conv+silu out (xs | B | C)
__device__ __align__(128) float2 g_dtdA[NBL * NHEADS];              // (dt, exp(dt*A)) packed
__device__ __align__(128) float  g_y   [(size_t)NBL * D_INNER];     // scan out, normed in-place
__device__ __align__(128) float  g_S   [(size_t)32 * NCH * HEADDIM * D_STATE]; // chunk states (134MB)
__device__ __align__(128) float  g_cumP[NBL * NHEADS];              // within-chunk cumprod of dA

// ---------------- helpers ----------------
__device__ __forceinline__ uint64_t pack2(float lo, float hi) {
    uint64_t r; asm("mov.b64 %0, {%1, %2};" : "=l"(r) : "f"(lo), "f"(hi)); return r;
}
__device__ __forceinline__ void unpack2(uint64_t v, float& lo, float& hi) {
    asm("mov.b64 {%0, %1}, %2;" : "=f"(lo), "=f"(hi) : "l"(v));
}
__device__ __forceinline__ uint64_t fma2(uint64_t a, uint64_t b, uint64_t c) {
    uint64_t d; asm("fma.rn.f32x2 %0, %1, %2, %3;" : "=l"(d) : "l"(a), "l"(b), "l"(c)); return d;
}
__device__ __forceinline__ uint64_t mul2(uint64_t a, uint64_t b) {
    uint64_t d; asm("mul.rn.f32x2 %0, %1, %2;" : "=l"(d) : "l"(a), "l"(b)); return d;
}
__device__ __forceinline__ uint32_t f2tf32(float f) {
    uint32_t r; asm("cvt.rna.tf32.f32 %0, %1;" : "=r"(r) : "f"(f)); return r;
}
// Reduce 8 per-thread values over 32 lanes with 9 shuffles.
// Returns: lane L holds full sum of v[L & 7].
__device__ __forceinline__ float reduce8(const float* v, int lane) {
    float A  = (lane & 1) ? v[1] : v[0];
    float As = (lane & 1) ? v[0] : v[1];
    A += __shfl_xor_sync(0xffffffffu, As, 1);
    float B  = (lane & 1) ? v[3] : v[2];
    float Bs = (lane & 1) ? v[2] : v[3];
    B += __shfl_xor_sync(0xffffffffu, Bs, 1);
    float C  = (lane & 1) ? v[5] : v[4];
    float Cs = (lane & 1) ? v[4] : v[5];
    C += __shfl_xor_sync(0xffffffffu, Cs, 1);
    float D  = (lane & 1) ? v[7] : v[6];
    float Ds = (lane & 1) ? v[6] : v[7];
    D += __shfl_xor_sync(0xffffffffu, Ds, 1);
    float E  = (lane & 2) ? B : A;
    float Es = (lane & 2) ? A : B;
    E += __shfl_xor_sync(0xffffffffu, Es, 2);
    float F  = (lane & 2) ? D : C;
    float Fs = (lane & 2) ? C : D;
    F += __shfl_xor_sync(0xffffffffu, Fs, 2);
    float G  = (lane & 4) ? F : E;
    float Gs = (lane & 4) ? E : F;
    G += __shfl_xor_sync(0xffffffffu, Gs, 4);
    G += __shfl_xor_sync(0xffffffffu, G, 8);
    G += __shfl_xor_sync(0xffffffffu, G, 16);
    return G;
}

#define MMA_TF32(c, a, b) \
    asm volatile("mma.sync.aligned.m16n8k8.row.col.f32.tf32.tf32.f32 " \
        "{%0,%1,%2,%3}, {%4,%5,%6,%7}, {%8,%9}, {%0,%1,%2,%3};" \
        : "+f"((c)[0]), "+f"((c)[1]), "+f"((c)[2]), "+f"((c)[3]) \
        : "r"((a)[0]), "r"((a)[1]), "r"((a)[2]), "r"((a)[3]), \
          "r"((b)[0]), "r"((b)[1]))

// =====================================================================
// GEMM1 (tf32 tensor core): zxbcdt[m][n] = sum_k x[b][k][l]*W[n][k].
// Covers n in [0, 2304) only; dt cols via dtprep.
// =====================================================================
__global__ __launch_bounds__(256) void gemm1_kernel(const float* __restrict__ x,
                                                    const float* __restrict__ W) {
    __shared__ uint32_t As[16][136];   // [k][m], tf32 bits
    __shared__ uint32_t Bs[128][20];   // [n][k], tf32 bits
    const int tid = threadIdx.x;
    const int m0 = blockIdx.y * 128;
    const int n0 = blockIdx.x * 128;
    const int b = m0 >> 12, l0 = m0 & 4095;
    const float* Ap = x + (size_t)b * DIM * LSEQ + l0;
    const float* Bp = W + (size_t)n0 * DIM;

    const int ka = tid >> 4;           // 0..15
    const int ma = (tid & 15) * 8;     // 0..120
    const int nb = tid >> 1;           // 0..127
    const int kb = (tid & 1) * 8;      // 0 or 8

    const int wid = tid >> 5, lane = tid & 31;
    const int wm = (wid >> 2) * 64;    // 0 or 64
    const int wn = (wid & 3) * 32;     // 0..96
    const int gid = lane >> 2, tig = lane & 3;

    float c[4][4][4];
#pragma unroll
    for (int i = 0; i < 4; i++)
#pragma unroll
        for (int j = 0; j < 4; j++)
#pragma unroll
            for (int q = 0; q < 4; q++) c[i][j][q] = 0.f;

    for (int k0 = 0; k0 < DIM; k0 += 16) {
        float4 av0 = *(const float4*)(Ap + (size_t)(k0 + ka) * LSEQ + ma);
        float4 av1 = *(const float4*)(Ap + (size_t)(k0 + ka) * LSEQ + ma + 4);
        float4 bv0 = *(const float4*)(Bp + (size_t)nb * DIM + k0 + kb);
        float4 bv1 = *(const float4*)(Bp + (size_t)nb * DIM + k0 + kb + 4);
        __syncthreads();
        {
            uint4 t;
            t.x = f2tf32(av0.x); t.y = f2tf32(av0.y); t.z = f2tf32(av0.z); t.w = f2tf32(av0.w);
            *(uint4*)&As[ka][ma] = t;
            t.x = f2tf32(av1.x); t.y = f2tf32(av1.y); t.z = f2tf32(av1.z); t.w = f2tf32(av1.w);
            *(uint4*)&As[ka][ma + 4] = t;
            t.x = f2tf32(bv0.x); t.y = f2tf32(bv0.y); t.z = f2tf32(bv0.z); t.w = f2tf32(bv0.w);
            *(uint4*)&Bs[nb][kb] = t;
            t.x = f2tf32(bv1.x); t.y = f2tf32(bv1.y); t.z = f2tf32(bv1.z); t.w = f2tf32(bv1.w);
            *(uint4*)&Bs[nb][kb + 4] = t;
        }
        __syncthreads();
#pragma unroll
        for (int kk = 0; kk < 16; kk += 8) {
            uint32_t af[4][4], bf[4][2];
#pragma unroll
            for (int mi = 0; mi < 4; mi++) {
                const int mr = wm + mi * 16 + gid;
                af[mi][0] = As[kk + tig][mr];
                af[mi][1] = As[kk + tig][mr + 8];
                af[mi][2] = As[kk + tig + 4][mr];
                af[mi][3] = As[kk + tig + 4][mr + 8];
            }
#pragma unroll
            for (int ni = 0; ni < 4; ni++) {
                const int nr = wn + ni * 8 + gid;
                bf[ni][0] = Bs[nr][kk + tig];
                bf[ni][1] = Bs[nr][kk + tig + 4];
            }
#pragma unroll
            for (int mi = 0; mi < 4; mi++)
#pragma unroll
                for (int ni = 0; ni < 4; ni++)
                    MMA_TF32(c[mi][ni], af[mi], bf[ni]);
        }
    }

#pragma unroll
    for (int mi = 0; mi < 4; mi++) {
#pragma unroll
        for (int ni = 0; ni < 4; ni++) {
            const int row = m0 + wm + mi * 16 + gid;
            const int col = n0 + wn + ni * 8 + tig * 2;
            float2 v0; v0.x = c[mi][ni][0]; v0.y = c[mi][ni][1];
            float2 v1; v1.x = c[mi][ni][2]; v1.y = c[mi][ni][3];
            *(float2*)(g_zx + (size_t)row * D_IN_PROJ + col)       = v0;
            *(float2*)(g_zx + (size_t)(row + 8) * D_IN_PROJ + col) = v1;
        }
    }
}

// =====================================================================
// dtprep: exact fp32 dt projection + softplus + dA.
// =====================================================================
__global__ __launch_bounds__(256) void dtprep_kernel(const float* __restrict__ x,
                                                     const float* __restrict__ W,
                                                     const float* __restrict__ dt_bias,
                                                     const float* __restrict__ A_log) {
    __shared__ float Ws[8][516];
    const int tid = threadIdx.x;
    for (int i = tid; i < 8 * DIM; i += 256)
        Ws[i >> 9][i & 511] = W[(size_t)(D_INNER + CONV_DIM) * DIM + i];
    __syncthreads();

    const int gid = blockIdx.x * 256 + tid;   // < NBL*NHEADS
    const int bl = gid >> 3, h = gid & 7;
    const int b = bl >> 12, l = bl & 4095;
    const float* xp = x + (size_t)b * DIM * LSEQ + l;
    float a0 = 0.f, a1 = 0.f, a2 = 0.f, a3 = 0.f;
#pragma unroll 4
    for (int k = 0; k < DIM; k += 4) {
        a0 = fmaf(xp[(size_t)(k + 0) * LSEQ], Ws[h][k + 0], a0);
        a1 = fmaf(xp[(size_t)(k + 1) * LSEQ], Ws[h][k + 1], a1);
        a2 = fmaf(xp[(size_t)(k + 2) * LSEQ], Ws[h][k + 2], a2);
        a3 = fmaf(xp[(size_t)(k + 3) * LSEQ], Ws[h][k + 3], a3);
    }
    float v = (a0 + a1) + (a2 + a3) + dt_bias[h];
    float dt = (v > 20.f) ? v : log1pf(expf(v));
    float A = -expf(A_log[h]);
    g_dtdA[gid] = make_float2(dt, expf(dt * A));
}

// =====================================================================
// conv: causal depthwise conv over l (width 4) + bias, then SiLU.
// =====================================================================
__global__ __launch_bounds__(256) void conv_kernel(const float* __restrict__ conv_w,
                                                   const float* __restrict__ conv_b) {
    const int gid = blockIdx.x * 256 + threadIdx.x;   // exactly NBL*CONV_DIM
    const int bl = gid / CONV_DIM;
    const int c  = gid - bl * CONV_DIM;
    const int l  = bl & 4095;
    const float w0 = conv_w[c * 4 + 0], w1 = conv_w[c * 4 + 1];
    const float w2 = conv_w[c * 4 + 2], w3 = conv_w[c * 4 + 3];
    const float* base = g_zx + (size_t)bl * D_IN_PROJ + D_INNER + c;
    float acc = conv_b[c];
    if (l >= 3) {
        acc += base[-3 * D_IN_PROJ] * w0;
        acc += base[-2 * D_IN_PROJ] * w1;
        acc += base[-1 * D_IN_PROJ] * w2;
        acc += base[0] * w3;
    } else {
        if (l >= 2) acc += base[-2 * D_IN_PROJ] * w1;
        if (l >= 1) acc += base[-1 * D_IN_PROJ] * w2;
        acc += base[0] * w3;
    }
    g_conv[gid] = acc / (1.f + expf(-acc));
}

// =====================================================================
// ssd_intra: intra-chunk scan via tensor cores. One block per (bh, c).
// G = C@B^T (K=128) -> M = causal exp/dt scaling -> Y = M@X (+D*x),
// S_local = X^T @ (w.B). Dynamic smem ~150 KB, 1 block/SM.
// =====================================================================
#define SM_C   0                                  // Cs[64][132]
#define SM_B   (64 * 132)                         // Bs[64][132]
#define SM_XT  (2 * 64 * 132)                     // XT[128][67]  (X transposed)
#define SM_M   (2 * 64 * 132 + 128 * 67)          // Ms[64][68]
#define SM_BW  (2 * 64 * 132 + 128 * 67 + 64*68)  // BW[128][67]  (w.B transposed)
#define SM_DT  (2 * 64 * 132 + 2 * 128 * 67 + 64 * 68)
#define SM_CDT (SM_DT + 64)
#define SM_WORDS (SM_CDT + 64)
#define SSD_SMEM_BYTES (SM_WORDS * 4)

__global__ __launch_bounds__(256) void ssd_intra_kernel(const float* __restrict__ A_log,
                                                        const float* __restrict__ D_param) {
    extern __shared__ uint32_t sm[];
    uint32_t* Cs = sm + SM_C;
    uint32_t* Bs = sm + SM_B;
    uint32_t* XT = sm + SM_XT;
    uint32_t* Ms = sm + SM_M;
    uint32_t* BW = sm + SM_BW;
    float* dts  = (float*)(sm + SM_DT);
    float* cdts = (float*)(sm + SM_CDT);

    const int tid = threadIdx.x;
    const int c = blockIdx.x, bh = blockIdx.y;
    const int b = bh >> 3, h = bh & 7;
    const int blbase = b << 12;
    const int t0g = blbase + c * TCH;
    const float Ah = -expf(A_log[h]);
    const float Dh = D_param[h];
    const int wid = tid >> 5, lane = tid & 31;
    const int gid = lane >> 2, tig = lane & 3;

    // ---- stage dt + in-chunk cumsum (exact fp32) ----
    if (tid < TCH) dts[tid] = g_dtdA[(t0g + tid) * NHEADS + h].x;
    __syncthreads();
    if (tid < 32) {
        float v0 = dts[2 * tid], v1 = dts[2 * tid + 1];
        float s = v0 + v1, sc = s;
#pragma unroll
        for (int off = 1; off < 32; off <<= 1) {
            float u = __shfl_up_sync(0xffffffffu, sc, off);
            if (tid >= off) sc += u;
        }
        float excl = __shfl_up_sync(0xffffffffu, sc, 1);
        if (tid == 0) excl = 0.f;
        cdts[2 * tid]     = excl + v0;
        cdts[2 * tid + 1] = excl + v0 + v1;
    }
    // ---- stage C, B (row-major [j][n]) and X^T ([p][j]) as tf32 ----
#pragma unroll
    for (int q = 0; q < 8; q++) {
        const int idx = q * 256 + tid;           // 0..2047 float4 slots
        const int j = idx >> 5, n4 = (idx & 31) * 4;
        const float* row = g_conv + (size_t)(t0g + j) * CONV_DIM;
        float4 bv = *(const float4*)(row + D_INNER + n4);
        float4 cv = *(const float4*)(row + D_INNER + D_STATE + n4);
        float4 xv = *(const float4*)(row + h * HEADDIM + n4);
        uint4 u;
        u.x = f2tf32(cv.x); u.y = f2tf32(cv.y); u.z = f2tf32(cv.z); u.w = f2tf32(cv.w);
        *(uint4*)&Cs[j * 132 + n4] = u;
        u.x = f2tf32(bv.x); u.y = f2tf32(bv.y); u.z = f2tf32(bv.z); u.w = f2tf32(bv.w);
        *(uint4*)&Bs[j * 132 + n4] = u;
        XT[(n4 + 0) * 67 + j] = f2tf32(xv.x);
        XT[(n4 + 1) * 67 + j] = f2tf32(xv.y);
        XT[(n4 + 2) * 67 + j] = f2tf32(xv.z);
        XT[(n4 + 3) * 67 + j] = f2tf32(xv.w);
    }
    __syncthreads();

    // ---- Phase A: G[t][j] = C_t . B_j  (64x64, K=128), then scale -> Ms ----
    {
        const int wm = (wid >> 1) * 16, wn = (wid & 1) * 32;
        float cG[4][4];
#pragma unroll
        for (int i = 0; i < 4; i++)
#pragma unroll
            for (int q = 0; q < 4; q++) cG[i][q] = 0.f;
#pragma unroll
        for (int kk = 0; kk < 128; kk += 8) {
            uint32_t af[4];
            af[0] = Cs[(wm + gid) * 132 + kk + tig];
            af[1] = Cs[(wm + gid + 8) * 132 + kk + tig];
            af[2] = Cs[(wm + gid) * 132 + kk + tig + 4];
            af[3] = Cs[(wm + gid + 8) * 132 + kk + tig + 4];
#pragma unroll
            for (int ni = 0; ni < 4; ni++) {
                uint32_t bf[2];
                bf[0] = Bs[(wn + ni * 8 + gid) * 132 + kk + tig];
                bf[1] = Bs[(wn + ni * 8 + gid) * 132 + kk + tig + 4];
                MMA_TF32(cG[ni], af, bf);
            }
        }
#pragma unroll
        for (int ni = 0; ni < 4; ni++) {
#pragma unroll
            for (int q = 0; q < 4; q++) {
                const int t = wm + gid + (q >> 1) * 8;
                const int j = wn + ni * 8 + tig * 2 + (q & 1);
                float m = 0.f;
                if (t >= j) m = __expf(Ah * (cdts[t] - cdts[j])) * dts[j] * cG[ni][q];
                Ms[t * 68 + j] = f2tf32(m);
            }
        }
    }
    __syncthreads();

    // ---- Phase C: Y_intra = M @ X  (64x128, K=64), epilogue += D*x ----
    {
        const int wm = (wid >> 1) * 16, wn = (wid & 1) * 64;
        float cY[8][4];
#pragma unroll
        for (int i = 0; i < 8; i++)
#pragma unroll
            for (int q = 0; q < 4; q++) cY[i][q] = 0.f;
#pragma unroll
        for (int kk = 0; kk < 64; kk += 8) {
            uint32_t af[4];
            af[0] = Ms[(wm + gid) * 68 + kk + tig];
            af[1] = Ms[(wm + gid + 8) * 68 + kk + tig];
            af[2] = Ms[(wm + gid) * 68 + kk + tig + 4];
            af[3] = Ms[(wm + gid + 8) * 68 + kk + tig + 4];
#pragma unroll
            for (int ni = 0; ni < 8; ni++) {
                uint32_t bf[2];
                bf[0] = XT[(wn + ni * 8 + gid) * 67 + kk + tig];
                bf[1] = XT[(wn + ni * 8 + gid) * 67 + kk + tig + 4];
                MMA_TF32(cY[ni], af, bf);
            }
        }
#pragma unroll
        for (int ni = 0; ni < 8; ni++) {
            const int p = wn + ni * 8 + tig * 2;
            const int r0 = t0g + wm + gid, r1 = r0 + 8;
            float2 x0 = *(const float2*)(g_conv + (size_t)r0 * CONV_DIM + h * HEADDIM + p);
            float2 x1 = *(const float2*)(g_conv + (size_t)r1 * CONV_DIM + h * HEADDIM + p);
            float2 y0, y1;
            y0.x = cY[ni][0] + Dh * x0.x; y0.y = cY[ni][1] + Dh * x0.y;
            y1.x = cY[ni][2] + Dh * x1.x; y1.y = cY[ni][3] + Dh * x1.y;
            *(float2*)(g_y + (size_t)r0 * D_INNER + h * HEADDIM + p) = y0;
            *(float2*)(g_y + (size_t)r1 * D_INNER + h * HEADDIM + p) = y1;
        }
    }

    // ---- Phase D staging: BW[n][j] = w_j * B_j[n],
    //      w_j = exp(Ah*(cdt_63 - cdt_j)) * dt_j ----
    {
        const float cdT = cdts[TCH - 1];
#pragma unroll
        for (int q = 0; q < 8; q++) {
            const int idx = q * 256 + tid;
            const int j = idx >> 5, n4 = (idx & 31) * 4;
            const float w = __expf(Ah * (cdT - cdts[j])) * dts[j];
            uint4 u = *(uint4*)&Bs[j * 132 + n4];
            BW[(n4 + 0) * 67 + j] = f2tf32(__uint_as_float(u.x) * w);
            BW[(n4 + 1) * 67 + j] = f2tf32(__uint_as_float(u.y) * w);
            BW[(n4 + 2) * 67 + j] = f2tf32(__uint_as_float(u.z) * w);
            BW[(n4 + 3) * 67 + j] = f2tf32(__uint_as_float(u.w) * w);
        }
    }
    __syncthreads();

    // ---- Phase D: S_local[p][n] = sum_j X[j][p] * w_j B_j[n]  (128x128, K=64) ----
    {
        const int wm = (wid >> 2) * 64, wn = (wid & 3) * 32;
        float cS[4][4][4];
#pragma unroll
        for (int mi = 0; mi < 4; mi++)
#pragma unroll
            for (int ni = 0; ni < 4; ni++)
#pragma unroll
                for (int q = 0; q < 4; q++) cS[mi][ni][q] = 0.f;
#pragma unroll
        for (int kk = 0; kk < 64; kk += 8) {
            uint32_t af[4][4], bf[4][2];
#pragma unroll
            for (int mi = 0; mi < 4; mi++) {
                const int mr = wm + mi * 16 + gid;
                af[mi][0] = XT[mr * 67 + kk + tig];
                af[mi][1] = XT[(mr + 8) * 67 + kk + tig];
                af[mi][2] = XT[mr * 67 + kk + tig + 4];
                af[mi][3] = XT[(mr + 8) * 67 + kk + tig + 4];
            }
#pragma unroll
            for (int ni = 0; ni < 4; ni++) {
                const int nr = wn + ni * 8 + gid;
                bf[ni][0] = BW[nr * 67 + kk + tig];
                bf[ni][1] = BW[nr * 67 + kk + tig + 4];
            }
#pragma unroll
            for (int mi = 0; mi < 4; mi++)
#pragma unroll
                for (int ni = 0; ni < 4; ni++)
                    MMA_TF32(cS[mi][ni], af[mi], bf[ni]);
        }
        float* Sp = g_S + (size_t)(bh * NCH + c) * HEADDIM * D_STATE;
#pragma unroll
        for (int mi = 0; mi < 4; mi++) {
#pragma unroll
            for (int ni = 0; ni < 4; ni++) {
                const int p = wm + mi * 16 + gid;
                const int n = wn + ni * 8 + tig * 2;
                float2 v0; v0.x = cS[mi][ni][0]; v0.y = cS[mi][ni][1];
                float2 v1; v1.x = cS[mi][ni][2]; v1.y = cS[mi][ni][3];
                *(float2*)(Sp + (size_t)p * D_STATE + n)       = v0;
                *(float2*)(Sp + (size_t)(p + 8) * D_STATE + n) = v1;
            }
        }
    }
}

// =====================================================================
// cumP: warp-parallel prefix product per (bh, chunk). 2048 chains of 64.
// =====================================================================
__global__ __launch_bounds__(256) void cumP_kernel() {
    const int gw   = blockIdx.x * 8 + (threadIdx.x >> 5);   // 0..2047
    const int lane = threadIdx.x & 31;
    const int bh = gw >> 6, c = gw & 63;
    const int b = bh >> 3, h = bh & 7;
    const int blbase = b << 12;
    const int tbase = c * TCH + lane * 2;

    float v0 = g_dtdA[(blbase + tbase) * NHEADS + h].y;
    float v1 = g_dtdA[(blbase + tbase + 1) * NHEADS + h].y;
    float scan = v0 * v1;
#pragma unroll
    for (int off = 1; off < 32; off <<= 1) {
        float u = __shfl_up_sync(0xffffffffu, scan, off);
        if (lane >= off) scan *= u;
    }
    float excl = __shfl_up_sync(0xffffffffu, scan, 1);
    if (lane == 0) excl = 1.f;
    g_cumP[(blbase + tbase) * NHEADS + h]     = excl * v0;
    g_cumP[(blbase + tbase + 1) * NHEADS + h] = excl * v0 * v1;
}

// =====================================================================
// pass B: chunk carry recurrence over 64 chunks.
// S_in_{c+1} = SL_c + Ptot_c * S_in_c; overwrites g_S[c] with S_in_c.
// =====================================================================
__global__ __launch_bounds__(256) void passB_kernel() {
    const int gid = blockIdx.x * 256 + threadIdx.x;   // 131072
    const int n0 = (gid & 31) * 4;
    const int p  = (gid >> 5) & 127;
    const int bh = gid >> 12;
    const int b = bh >> 3, h = bh & 7;
    const int blbase = b << 12;
    float4 carry = make_float4(0.f, 0.f, 0.f, 0.f);
#pragma unroll 4
    for (int c = 0; c < NCH; c++) {
        float* sp = g_S + ((size_t)(bh * NCH + c) * HEADDIM + p) * D_STATE + n0;
        float4 SL = *(float4*)sp;
        *(float4*)sp = carry;
        float Pt = g_cumP[(blbase + c * TCH + TCH - 1) * NHEADS + h];
        carry.x = SL.x + Pt * carry.x;
        carry.y = SL.y + Pt * carry.y;
        carry.z = SL.z + Pt * carry.z;
        carry.w = SL.w + Pt * carry.w;
    }
}

// =====================================================================
// fixup (Y_inter): y_t += cumP_t * (C_t . S_in_c). Chunks 1..63.
// 8 p-rows per warp, reduce8. Grid (pt:4, c-1:63, bh:32).
// =====================================================================
__global__ __launch_bounds__(128) void fixup_kernel() {
    const int tid = threadIdx.x, lane = tid & 31, w = tid >> 5;
    const int pt = blockIdx.x;          // 0..3
    const int c  = blockIdx.y + 1;      // 1..63
    const int bh = blockIdx.z;
    const int b = bh >> 3, h = bh & 7;
    const int p0 = pt * 32 + w * 8, n0 = lane * 4;
    const int blbase = b << 12;
    const int t0 = c * TCH;

    uint64_t S[8][2];
    {
        const float* sp = g_S + ((size_t)(bh * NCH + c) * HEADDIM + p0) * D_STATE + n0;
#pragma unroll
        for (int i = 0; i < 8; i++) {
            ulonglong2 r = *(const ulonglong2*)(sp + (size_t)i * D_STATE);
            S[i][0] = r.x; S[i][1] = r.y;
        }
    }
    const float* Cp = g_conv + (size_t)blbase * CONV_DIM + D_INNER + D_STATE + n0;
    const float* Pp = g_cumP + blbase * NHEADS + h;
    float* Yp = g_y + (size_t)blbase * D_INNER + h * HEADDIM + p0;

#pragma unroll 2
    for (int t = t0; t < t0 + TCH; t++) {
        ulonglong2 Cv = *(const ulonglong2*)(Cp + (size_t)t * CONV_DIM);
        float cp = Pp[t * NHEADS];
        float v[8];
#pragma unroll
        for (int i = 0; i < 8; i++) {
            uint64_t u = fma2(S[i][1], Cv.y, mul2(S[i][0], Cv.x));
            float lo, hi; unpack2(u, lo, hi);
            v[i] = lo + hi;
        }
        float G = reduce8(v, lane);
        if (lane < 8) {
            float* yp = Yp + (size_t)t * D_INNER + lane;
            *yp += cp * G;
        }
    }
}

// =====================================================================
// mulnorm: y = y * silu(z); y = y * rsqrt(mean(y^2)+1e-5) * norm_w
// =====================================================================
__global__ __launch_bounds__(256) void mulnorm_kernel(const float* __restrict__ norm_w) {
    __shared__ float red[8];
    __shared__ float rinv;
    const int bl = blockIdx.x, tid = threadIdx.x;
    const int lane = tid & 31, w = tid >> 5;
    float4 yv = *(const float4*)(g_y + (size_t)bl * D_INNER + tid * 4);
    float4 zv = *(const float4*)(g_zx + (size_t)bl * D_IN_PROJ + tid * 4);
    float4 t;
    t.x = yv.x * (zv.x / (1.f + expf(-zv.x)));
    t.y = yv.y * (zv.y / (1.f + expf(-zv.y)));
    t.z = yv.z * (zv.z / (1.f + expf(-zv.z)));
    t.w = yv.w * (zv.w / (1.f + expf(-zv.w)));
    float ss = t.x * t.x + t.y * t.y + t.z * t.z + t.w * t.w;
#pragma unroll
    for (int off = 16; off > 0; off >>= 1) ss += __shfl_xor_sync(0xffffffffu, ss, off);
    if (lane == 0) red[w] = ss;
    __syncthreads();
    if (tid == 0) {
        float tot = 0.f;
#pragma unroll
        for (int i = 0; i < 8; i++) tot += red[i];
        rinv = rsqrtf(tot * (1.f / (float)D_INNER) + 1e-5f);
    }
    __syncthreads();
    const float r = rinv;
    float4 w4 = *(const float4*)(norm_w + tid * 4);
    t.x *= r * w4.x; t.y *= r * w4.y; t.z *= r * w4.z; t.w *= r * w4.w;
    *(float4*)(g_y + (size_t)bl * D_INNER + tid * 4) = t;
}

// =====================================================================
// GEMM2 (tf32 tensor core): out[b][d][l] = sum_e Wo[d][e]*y[bl][e] + x.
// =====================================================================
__global__ __launch_bounds__(256) void gemm2_kernel(const float* __restrict__ Wo,
                                                    const float* __restrict__ x,
                                                    float* __restrict__ out) {
    __shared__ uint32_t As[128][20];   // [d][k]
    __shared__ uint32_t Bs[128][20];   // [l][k]
    const int tid = threadIdx.x;
    const int l0 = blockIdx.x * 128;
    const int d0 = blockIdx.y * 128;
    const int b  = blockIdx.z;
    const float* yp = g_y + (size_t)(b * LSEQ + l0) * D_INNER;

    const int rb = tid >> 1;           // 0..127
    const int kb = (tid & 1) * 8;      // 0 or 8

    const int wid = tid >> 5, lane = tid & 31;
    const int wm = (wid >> 2) * 64;
    const int wn = (wid & 3) * 32;
    const int gid = lane >> 2, tig = lane & 3;

    float c[4][4][4];
#pragma unroll
    for (int i = 0; i < 4; i++)
#pragma unroll
        for (int j = 0; j < 4; j++)
#pragma unroll
            for (int q = 0; q < 4; q++) c[i][j][q] = 0.f;

    for (int k0 = 0; k0 < D_INNER; k0 += 16) {
        float4 av0 = *(const float4*)(Wo + (size_t)(d0 + rb) * D_INNER + k0 + kb);
        float4 av1 = *(const float4*)(Wo + (size_t)(d0 + rb) * D_INNER + k0 + kb + 4);
        float4 bv0 = *(const float4*)(yp + (size_t)rb * D_INNER + k0 + kb);
        float4 bv1 = *(const float4*)(yp + (size_t)rb * D_INNER + k0 + kb + 4);
        __syncthreads();
        {
            uint4 t;
            t.x = f2tf32(av0.x); t.y = f2tf32(av0.y); t.z = f2tf32(av0.z); t.w = f2tf32(av0.w);
            *(uint4*)&As[rb][kb] = t;
            t.x = f2tf32(av1.x); t.y = f2tf32(av1.y); t.z = f2tf32(av1.z); t.w = f2tf32(av1.w);
            *(uint4*)&As[rb][kb + 4] = t;
            t.x = f2tf32(bv0.x); t.y = f2tf32(bv0.y); t.z = f2tf32(bv0.z); t.w = f2tf32(bv0.w);
            *(uint4*)&Bs[rb][kb] = t;
            t.x = f2tf32(bv1.x); t.y = f2tf32(bv1.y); t.z = f2tf32(bv1.z); t.w = f2tf32(bv1.w);
            *(uint4*)&Bs[rb][kb + 4] = t;
        }
        __syncthreads();
#pragma unroll
        for (int kk = 0; kk < 16; kk += 8) {
            uint32_t af[4][4], bf[4][2];
#pragma unroll
            for (int mi = 0; mi < 4; mi++) {
                const int mr = wm + mi * 16 + gid;
                af[mi][0] = As[mr][kk + tig];
                af[mi][1] = As[mr + 8][kk + tig];
                af[mi][2] = As[mr][kk + tig + 4];
                af[mi][3] = As[mr + 8][kk + tig + 4];
            }
#pragma unroll
            for (int ni = 0; ni < 4; ni++) {
                const int nr = wn + ni * 8 + gid;
                bf[ni][0] = Bs[nr][kk + tig];
                bf[ni][1] = Bs[nr][kk + tig + 4];
            }
#pragma unroll
            for (int mi = 0; mi < 4; mi++)
#pragma unroll
                for (int ni = 0; ni < 4; ni++)
                    MMA_TF32(c[mi][ni], af[mi], bf[ni]);
        }
    }

    const size_t base = (size_t)b * DIM * LSEQ;
#pragma unroll
    for (int mi = 0; mi < 4; mi++) {
#pragma unroll
        for (int ni = 0; ni < 4; ni++) {
            const int d = d0 + wm + mi * 16 + gid;
            const int l = l0 + wn + ni * 8 + tig * 2;
            const size_t off0 = base + (size_t)d * LSEQ + l;
            const size_t off1 = off0 + (size_t)8 * LSEQ;
            float2 x0 = *(const float2*)(x + off0);
            float2 x1 = *(const float2*)(x + off1);
            float2 o0; o0.x = c[mi][ni][0] + x0.x; o0.y = c[mi][ni][1] + x0.y;
            float2 o1; o1.x = c[mi][ni][2] + x1.x; o1.y = c[mi][ni][3] + x1.y;
            *(float2*)(out + off0) = o0;
            *(float2*)(out + off1) = o1;
        }
    }
}

// =====================================================================
extern "C" void kernel_launch(void* const* d_in, const int* in_sizes, int n_in,
                              void* d_out, int out_size) {
    const float* x          = (const float*)d_in[0];
    const float* in_proj_w  = (const float*)d_in[1];
    const float* conv_w     = (const float*)d_in[2];
    const float* conv_b     = (const float*)d_in[3];
    const float* dt_bias    = (const float*)d_in[4];
    const float* A_log      = (const float*)d_in[5];
    const float* D_param    = (const float*)d_in[6];
    const float* norm_w     = (const float*)d_in[7];
    const float* out_proj_w = (const float*)d_in[8];
    float* out = (float*)d_out;

    // allow >48KB dynamic smem for the SSD kernel (idempotent)
    cudaFuncSetAttribute(ssd_intra_kernel,
                         cudaFuncAttributeMaxDynamicSharedMemorySize, SSD_SMEM_BYTES);

    // 1. exact fp32 dt projection + softplus + dA
    dtprep_kernel<<<(NBL * NHEADS) / 256, 256>>>(x, in_proj_w, dt_bias, A_log);
    // 2. in_proj GEMM, tf32 tensor cores (cols 0..2303)
    gemm1_kernel<<<dim3(18, NBL / 128), 256>>>(x, in_proj_w);
    // 3. depthwise causal conv + SiLU
    conv_kernel<<<((size_t)NBL * CONV_DIM) / 256, 256>>>(conv_w, conv_b);
    // 4. SSD intra-chunk (tensor cores): Y_intra + chunk states
    ssd_intra_kernel<<<dim3(NCH, 32), 256, SSD_SMEM_BYTES>>>(A_log, D_param);
    // 5. within-chunk cumprod of dA
    cumP_kernel<<<256, 256>>>();
    // 6. chunk carry recurrence (pass B, 64 chunks)
    passB_kernel<<<(32 * HEADDIM * D_STATE / 4) / 256, 256>>>();
    // 7. inter-chunk fixup (exact fp32)
    fixup_kernel<<<dim3(4, NCH - 1, 32), 128>>>();
    // 8. gate + RMSNorm
    mulnorm_kernel<<<NBL, 256>>>(norm_w);
    // 9. out_proj GEMM, tf32 tensor cores + residual, transposed store
    gemm2_kernel<<<dim3(LSEQ / 128, DIM / 128, BSZ), 256>>>(out_proj_w, x, out);
}

// round 12
// speedup vs baseline: 1.0755x; 1.0755x over previous
#include <cuda_runtime.h>
#include <cuda_bf16.h>
#include <cstdint>

// ---------------- problem constants ----------------
#define BSZ        4
#define DIM        512
#define D_INNER    1024
#define HEADDIM    128
#define NHEADS     8
#define D_STATE    128
#define D_CONV     4
#define CONV_DIM   1280          // D_INNER + 2*D_STATE
#define D_IN_PROJ  2312          // 2*D_INNER + 2*D_STATE + NHEADS
#define LSEQ       4096          // 16*16*16
#define NBL        (BSZ * LSEQ)  // 16384 rows (b,l)
#define TCH        64            // SSD chunk length
#define NCH        (LSEQ / TCH)  // 64 chunks per (b)

// ---------------- device scratch (static globals; no allocation) ----------------
__device__ __align__(128) float  g_zx  [(size_t)NBL * D_IN_PROJ];   // in_proj out (z | xBC)
__device__ __align__(128) float  g_conv[(size_t)NBL * CONV_DIM];    // conv+silu out (xs | B | C)
__device__ __align__(128) float2 g_dtdA[NBL * NHEADS];              // (dt, exp(dt*A)) packed
__device__ __align__(128) float  g_y   [(size_t)NBL * D_INNER];     // scan out, normed in-place
__device__ __align__(128) float  g_S   [(size_t)32 * NCH * HEADDIM * D_STATE]; // chunk states (134MB)
__device__ __align__(128) float  g_cumP[NBL * NHEADS];              // within-chunk cumprod of dA

// ---------------- helpers ----------------
__device__ __forceinline__ uint32_t f2tf32(float f) {
    uint32_t r; asm("cvt.rna.tf32.f32 %0, %1;" : "=r"(r) : "f"(f)); return r;
}

#define MMA_TF32(c, a, b) \
    asm volatile("mma.sync.aligned.m16n8k8.row.col.f32.tf32.tf32.f32 " \
        "{%0,%1,%2,%3}, {%4,%5,%6,%7}, {%8,%9}, {%0,%1,%2,%3};" \
        : "+f"((c)[0]), "+f"((c)[1]), "+f"((c)[2]), "+f"((c)[3]) \
        : "r"((a)[0]), "r"((a)[1]), "r"((a)[2]), "r"((a)[3]), \
          "r"((b)[0]), "r"((b)[1]))

// =====================================================================
// GEMM1 (tf32 tensor core): zxbcdt[m][n] = sum_k x[b][k][l]*W[n][k].
// Covers n in [0, 2304) only; dt cols via dtprep.
// =====================================================================
__global__ __launch_bounds__(256) void gemm1_kernel(const float* __restrict__ x,
                                                    const float* __restrict__ W) {
    __shared__ uint32_t As[16][136];   // [k][m], tf32 bits
    __shared__ uint32_t Bs[128][20];   // [n][k], tf32 bits
    const int tid = threadIdx.x;
    const int m0 = blockIdx.y * 128;
    const int n0 = blockIdx.x * 128;
    const int b = m0 >> 12, l0 = m0 & 4095;
    const float* Ap = x + (size_t)b * DIM * LSEQ + l0;
    const float* Bp = W + (size_t)n0 * DIM;

    const int ka = tid >> 4;           // 0..15
    const int ma = (tid & 15) * 8;     // 0..120
    const int nb = tid >> 1;           // 0..127
    const int kb = (tid & 1) * 8;      // 0 or 8

    const int wid = tid >> 5, lane = tid & 31;
    const int wm = (wid >> 2) * 64;    // 0 or 64
    const int wn = (wid & 3) * 32;     // 0..96
    const int gid = lane >> 2, tig = lane & 3;

    float c[4][4][4];
#pragma unroll
    for (int i = 0; i < 4; i++)
#pragma unroll
        for (int j = 0; j < 4; j++)
#pragma unroll
            for (int q = 0; q < 4; q++) c[i][j][q] = 0.f;

    for (int k0 = 0; k0 < DIM; k0 += 16) {
        float4 av0 = *(const float4*)(Ap + (size_t)(k0 + ka) * LSEQ + ma);
        float4 av1 = *(const float4*)(Ap + (size_t)(k0 + ka) * LSEQ + ma + 4);
        float4 bv0 = *(const float4*)(Bp + (size_t)nb * DIM + k0 + kb);
        float4 bv1 = *(const float4*)(Bp + (size_t)nb * DIM + k0 + kb + 4);
        __syncthreads();
        {
            uint4 t;
            t.x = f2tf32(av0.x); t.y = f2tf32(av0.y); t.z = f2tf32(av0.z); t.w = f2tf32(av0.w);
            *(uint4*)&As[ka][ma] = t;
            t.x = f2tf32(av1.x); t.y = f2tf32(av1.y); t.z = f2tf32(av1.z); t.w = f2tf32(av1.w);
            *(uint4*)&As[ka][ma + 4] = t;
            t.x = f2tf32(bv0.x); t.y = f2tf32(bv0.y); t.z = f2tf32(bv0.z); t.w = f2tf32(bv0.w);
            *(uint4*)&Bs[nb][kb] = t;
            t.x = f2tf32(bv1.x); t.y = f2tf32(bv1.y); t.z = f2tf32(bv1.z); t.w = f2tf32(bv1.w);
            *(uint4*)&Bs[nb][kb + 4] = t;
        }
        __syncthreads();
#pragma unroll
        for (int kk = 0; kk < 16; kk += 8) {
            uint32_t af[4][4], bf[4][2];
#pragma unroll
            for (int mi = 0; mi < 4; mi++) {
                const int mr = wm + mi * 16 + gid;
                af[mi][0] = As[kk + tig][mr];
                af[mi][1] = As[kk + tig][mr + 8];
                af[mi][2] = As[kk + tig + 4][mr];
                af[mi][3] = As[kk + tig + 4][mr + 8];
            }
#pragma unroll
            for (int ni = 0; ni < 4; ni++) {
                const int nr = wn + ni * 8 + gid;
                bf[ni][0] = Bs[nr][kk + tig];
                bf[ni][1] = Bs[nr][kk + tig + 4];
            }
#pragma unroll
            for (int mi = 0; mi < 4; mi++)
#pragma unroll
                for (int ni = 0; ni < 4; ni++)
                    MMA_TF32(c[mi][ni], af[mi], bf[ni]);
        }
    }

#pragma unroll
    for (int mi = 0; mi < 4; mi++) {
#pragma unroll
        for (int ni = 0; ni < 4; ni++) {
            const int row = m0 + wm + mi * 16 + gid;
            const int col = n0 + wn + ni * 8 + tig * 2;
            float2 v0; v0.x = c[mi][ni][0]; v0.y = c[mi][ni][1];
            float2 v1; v1.x = c[mi][ni][2]; v1.y = c[mi][ni][3];
            *(float2*)(g_zx + (size_t)row * D_IN_PROJ + col)       = v0;
            *(float2*)(g_zx + (size_t)(row + 8) * D_IN_PROJ + col) = v1;
        }
    }
}

// =====================================================================
// dtprep: exact fp32 dt projection + softplus + dA.
// =====================================================================
__global__ __launch_bounds__(256) void dtprep_kernel(const float* __restrict__ x,
                                                     const float* __restrict__ W,
                                                     const float* __restrict__ dt_bias,
                                                     const float* __restrict__ A_log) {
    __shared__ float Ws[8][516];
    const int tid = threadIdx.x;
    for (int i = tid; i < 8 * DIM; i += 256)
        Ws[i >> 9][i & 511] = W[(size_t)(D_INNER + CONV_DIM) * DIM + i];
    __syncthreads();

    const int gid = blockIdx.x * 256 + tid;   // < NBL*NHEADS
    const int bl = gid >> 3, h = gid & 7;
    const int b = bl >> 12, l = bl & 4095;
    const float* xp = x + (size_t)b * DIM * LSEQ + l;
    float a0 = 0.f, a1 = 0.f, a2 = 0.f, a3 = 0.f;
#pragma unroll 4
    for (int k = 0; k < DIM; k += 4) {
        a0 = fmaf(xp[(size_t)(k + 0) * LSEQ], Ws[h][k + 0], a0);
        a1 = fmaf(xp[(size_t)(k + 1) * LSEQ], Ws[h][k + 1], a1);
        a2 = fmaf(xp[(size_t)(k + 2) * LSEQ], Ws[h][k + 2], a2);
        a3 = fmaf(xp[(size_t)(k + 3) * LSEQ], Ws[h][k + 3], a3);
    }
    float v = (a0 + a1) + (a2 + a3) + dt_bias[h];
    float dt = (v > 20.f) ? v : log1pf(expf(v));
    float A = -expf(A_log[h]);
    g_dtdA[gid] = make_float2(dt, expf(dt * A));
}

// =====================================================================
// conv: causal depthwise conv over l (width 4) + bias, then SiLU.
// =====================================================================
__global__ __launch_bounds__(256) void conv_kernel(const float* __restrict__ conv_w,
                                                   const float* __restrict__ conv_b) {
    const int gid = blockIdx.x * 256 + threadIdx.x;   // exactly NBL*CONV_DIM
    const int bl = gid / CONV_DIM;
    const int c  = gid - bl * CONV_DIM;
    const int l  = bl & 4095;
    const float w0 = conv_w[c * 4 + 0], w1 = conv_w[c * 4 + 1];
    const float w2 = conv_w[c * 4 + 2], w3 = conv_w[c * 4 + 3];
    const float* base = g_zx + (size_t)bl * D_IN_PROJ + D_INNER + c;
    float acc = conv_b[c];
    if (l >= 3) {
        acc += base[-3 * D_IN_PROJ] * w0;
        acc += base[-2 * D_IN_PROJ] * w1;
        acc += base[-1 * D_IN_PROJ] * w2;
        acc += base[0] * w3;
    } else {
        if (l >= 2) acc += base[-2 * D_IN_PROJ] * w1;
        if (l >= 1) acc += base[-1 * D_IN_PROJ] * w2;
        acc += base[0] * w3;
    }
    g_conv[gid] = acc / (1.f + expf(-acc));
}

// =====================================================================
// ssd_intra: intra-chunk scan via tensor cores. One block per (bh, c).
// =====================================================================
#define SM_C   0                                  // Cs[64][132]
#define SM_B   (64 * 132)                         // Bs[64][132]
#define SM_XT  (2 * 64 * 132)                     // XT[128][67]  (X transposed)
#define SM_M   (2 * 64 * 132 + 128 * 67)          // Ms[64][68]
#define SM_BW  (2 * 64 * 132 + 128 * 67 + 64*68)  // BW[128][67]  (w.B transposed)
#define SM_DT  (2 * 64 * 132 + 2 * 128 * 67 + 64 * 68)
#define SM_CDT (SM_DT + 64)
#define SM_WORDS (SM_CDT + 64)
#define SSD_SMEM_BYTES (SM_WORDS * 4)

__global__ __launch_bounds__(256) void ssd_intra_kernel(const float* __restrict__ A_log,
                                                        const float* __restrict__ D_param) {
    extern __shared__ uint32_t sm[];
    uint32_t* Cs = sm + SM_C;
    uint32_t* Bs = sm + SM_B;
    uint32_t* XT = sm + SM_XT;
    uint32_t* Ms = sm + SM_M;
    uint32_t* BW = sm + SM_BW;
    float* dts  = (float*)(sm + SM_DT);
    float* cdts = (float*)(sm + SM_CDT);

    const int tid = threadIdx.x;
    const int c = blockIdx.x, bh = blockIdx.y;
    const int b = bh >> 3, h = bh & 7;
    const int blbase = b << 12;
    const int t0g = blbase + c * TCH;
    const float Ah = -expf(A_log[h]);
    const float Dh = D_param[h];
    const int wid = tid >> 5, lane = tid & 31;
    const int gid = lane >> 2, tig = lane & 3;

    // ---- stage dt + in-chunk cumsum (exact fp32) ----
    if (tid < TCH) dts[tid] = g_dtdA[(t0g + tid) * NHEADS + h].x;
    __syncthreads();
    if (tid < 32) {
        float v0 = dts[2 * tid], v1 = dts[2 * tid + 1];
        float s = v0 + v1, sc = s;
#pragma unroll
        for (int off = 1; off < 32; off <<= 1) {
            float u = __shfl_up_sync(0xffffffffu, sc, off);
            if (tid >= off) sc += u;
        }
        float excl = __shfl_up_sync(0xffffffffu, sc, 1);
        if (tid == 0) excl = 0.f;
        cdts[2 * tid]     = excl + v0;
        cdts[2 * tid + 1] = excl + v0 + v1;
    }
    // ---- stage C, B (row-major [j][n]) and X^T ([p][j]) as tf32 ----
#pragma unroll
    for (int q = 0; q < 8; q++) {
        const int idx = q * 256 + tid;           // 0..2047 float4 slots
        const int j = idx >> 5, n4 = (idx & 31) * 4;
        const float* row = g_conv + (size_t)(t0g + j) * CONV_DIM;
        float4 bv = *(const float4*)(row + D_INNER + n4);
        float4 cv = *(const float4*)(row + D_INNER + D_STATE + n4);
        float4 xv = *(const float4*)(row + h * HEADDIM + n4);
        uint4 u;
        u.x = f2tf32(cv.x); u.y = f2tf32(cv.y); u.z = f2tf32(cv.z); u.w = f2tf32(cv.w);
        *(uint4*)&Cs[j * 132 + n4] = u;
        u.x = f2tf32(bv.x); u.y = f2tf32(bv.y); u.z = f2tf32(bv.z); u.w = f2tf32(bv.w);
        *(uint4*)&Bs[j * 132 + n4] = u;
        XT[(n4 + 0) * 67 + j] = f2tf32(xv.x);
        XT[(n4 + 1) * 67 + j] = f2tf32(xv.y);
        XT[(n4 + 2) * 67 + j] = f2tf32(xv.z);
        XT[(n4 + 3) * 67 + j] = f2tf32(xv.w);
    }
    __syncthreads();

    // ---- Phase A: G[t][j] = C_t . B_j  (64x64, K=128), then scale -> Ms ----
    {
        const int wm = (wid >> 1) * 16, wn = (wid & 1) * 32;
        float cG[4][4];
#pragma unroll
        for (int i = 0; i < 4; i++)
#pragma unroll
            for (int q = 0; q < 4; q++) cG[i][q] = 0.f;
#pragma unroll
        for (int kk = 0; kk < 128; kk += 8) {
            uint32_t af[4];
            af[0] = Cs[(wm + gid) * 132 + kk + tig];
            af[1] = Cs[(wm + gid + 8) * 132 + kk + tig];
            af[2] = Cs[(wm + gid) * 132 + kk + tig + 4];
            af[3] = Cs[(wm + gid + 8) * 132 + kk + tig + 4];
#pragma unroll
            for (int ni = 0; ni < 4; ni++) {
                uint32_t bf[2];
                bf[0] = Bs[(wn + ni * 8 + gid) * 132 + kk + tig];
                bf[1] = Bs[(wn + ni * 8 + gid) * 132 + kk + tig + 4];
                MMA_TF32(cG[ni], af, bf);
            }
        }
#pragma unroll
        for (int ni = 0; ni < 4; ni++) {
#pragma unroll
            for (int q = 0; q < 4; q++) {
                const int t = wm + gid + (q >> 1) * 8;
                const int j = wn + ni * 8 + tig * 2 + (q & 1);
                float m = 0.f;
                if (t >= j) m = __expf(Ah * (cdts[t] - cdts[j])) * dts[j] * cG[ni][q];
                Ms[t * 68 + j] = f2tf32(m);
            }
        }
    }
    __syncthreads();

    // ---- Phase C: Y_intra = M @ X  (64x128, K=64), epilogue += D*x ----
    {
        const int wm = (wid >> 1) * 16, wn = (wid & 1) * 64;
        float cY[8][4];
#pragma unroll
        for (int i = 0; i < 8; i++)
#pragma unroll
            for (int q = 0; q < 4; q++) cY[i][q] = 0.f;
#pragma unroll
        for (int kk = 0; kk < 64; kk += 8) {
            uint32_t af[4];
            af[0] = Ms[(wm + gid) * 68 + kk + tig];
            af[1] = Ms[(wm + gid + 8) * 68 + kk + tig];
            af[2] = Ms[(wm + gid) * 68 + kk + tig + 4];
            af[3] = Ms[(wm + gid + 8) * 68 + kk + tig + 4];
#pragma unroll
            for (int ni = 0; ni < 8; ni++) {
                uint32_t bf[2];
                bf[0] = XT[(wn + ni * 8 + gid) * 67 + kk + tig];
                bf[1] = XT[(wn + ni * 8 + gid) * 67 + kk + tig + 4];
                MMA_TF32(cY[ni], af, bf);
            }
        }
#pragma unroll
        for (int ni = 0; ni < 8; ni++) {
            const int p = wn + ni * 8 + tig * 2;
            const int r0 = t0g + wm + gid, r1 = r0 + 8;
            float2 x0 = *(const float2*)(g_conv + (size_t)r0 * CONV_DIM + h * HEADDIM + p);
            float2 x1 = *(const float2*)(g_conv + (size_t)r1 * CONV_DIM + h * HEADDIM + p);
            float2 y0, y1;
            y0.x = cY[ni][0] + Dh * x0.x; y0.y = cY[ni][1] + Dh * x0.y;
            y1.x = cY[ni][2] + Dh * x1.x; y1.y = cY[ni][3] + Dh * x1.y;
            *(float2*)(g_y + (size_t)r0 * D_INNER + h * HEADDIM + p) = y0;
            *(float2*)(g_y + (size_t)r1 * D_INNER + h * HEADDIM + p) = y1;
        }
    }

    // ---- Phase D staging: BW[n][j] = w_j * B_j[n] ----
    {
        const float cdT = cdts[TCH - 1];
#pragma unroll
        for (int q = 0; q < 8; q++) {
            const int idx = q * 256 + tid;
            const int j = idx >> 5, n4 = (idx & 31) * 4;
            const float w = __expf(Ah * (cdT - cdts[j])) * dts[j];
            uint4 u = *(uint4*)&Bs[j * 132 + n4];
            BW[(n4 + 0) * 67 + j] = f2tf32(__uint_as_float(u.x) * w);
            BW[(n4 + 1) * 67 + j] = f2tf32(__uint_as_float(u.y) * w);
            BW[(n4 + 2) * 67 + j] = f2tf32(__uint_as_float(u.z) * w);
            BW[(n4 + 3) * 67 + j] = f2tf32(__uint_as_float(u.w) * w);
        }
    }
    __syncthreads();

    // ---- Phase D: S_local[p][n] = sum_j X[j][p] * w_j B_j[n]  (128x128, K=64) ----
    {
        const int wm = (wid >> 2) * 64, wn = (wid & 3) * 32;
        float cS[4][4][4];
#pragma unroll
        for (int mi = 0; mi < 4; mi++)
#pragma unroll
            for (int ni = 0; ni < 4; ni++)
#pragma unroll
                for (int q = 0; q < 4; q++) cS[mi][ni][q] = 0.f;
#pragma unroll
        for (int kk = 0; kk < 64; kk += 8) {
            uint32_t af[4][4], bf[4][2];
#pragma unroll
            for (int mi = 0; mi < 4; mi++) {
                const int mr = wm + mi * 16 + gid;
                af[mi][0] = XT[mr * 67 + kk + tig];
                af[mi][1] = XT[(mr + 8) * 67 + kk + tig];
                af[mi][2] = XT[mr * 67 + kk + tig + 4];
                af[mi][3] = XT[(mr + 8) * 67 + kk + tig + 4];
            }
#pragma unroll
            for (int ni = 0; ni < 4; ni++) {
                const int nr = wn + ni * 8 + gid;
                bf[ni][0] = BW[nr * 67 + kk + tig];
                bf[ni][1] = BW[nr * 67 + kk + tig + 4];
            }
#pragma unroll
            for (int mi = 0; mi < 4; mi++)
#pragma unroll
                for (int ni = 0; ni < 4; ni++)
                    MMA_TF32(cS[mi][ni], af[mi], bf[ni]);
        }
        float* Sp = g_S + (size_t)(bh * NCH + c) * HEADDIM * D_STATE;
#pragma unroll
        for (int mi = 0; mi < 4; mi++) {
#pragma unroll
            for (int ni = 0; ni < 4; ni++) {
                const int p = wm + mi * 16 + gid;
                const int n = wn + ni * 8 + tig * 2;
                float2 v0; v0.x = cS[mi][ni][0]; v0.y = cS[mi][ni][1];
                float2 v1; v1.x = cS[mi][ni][2]; v1.y = cS[mi][ni][3];
                *(float2*)(Sp + (size_t)p * D_STATE + n)       = v0;
                *(float2*)(Sp + (size_t)(p + 8) * D_STATE + n) = v1;
            }
        }
    }
}

// =====================================================================
// cumP: warp-parallel prefix product per (bh, chunk). 2048 chains of 64.
// =====================================================================
__global__ __launch_bounds__(256) void cumP_kernel() {
    const int gw   = blockIdx.x * 8 + (threadIdx.x >> 5);   // 0..2047
    const int lane = threadIdx.x & 31;
    const int bh = gw >> 6, c = gw & 63;
    const int b = bh >> 3, h = bh & 7;
    const int blbase = b << 12;
    const int tbase = c * TCH + lane * 2;

    float v0 = g_dtdA[(blbase + tbase) * NHEADS + h].y;
    float v1 = g_dtdA[(blbase + tbase + 1) * NHEADS + h].y;
    float scan = v0 * v1;
#pragma unroll
    for (int off = 1; off < 32; off <<= 1) {
        float u = __shfl_up_sync(0xffffffffu, scan, off);
        if (lane >= off) scan *= u;
    }
    float excl = __shfl_up_sync(0xffffffffu, scan, 1);
    if (lane == 0) excl = 1.f;
    g_cumP[(blbase + tbase) * NHEADS + h]     = excl * v0;
    g_cumP[(blbase + tbase + 1) * NHEADS + h] = excl * v0 * v1;
}

// =====================================================================
// pass B: chunk carry recurrence over 64 chunks.
// =====================================================================
__global__ __launch_bounds__(256) void passB_kernel() {
    const int gid = blockIdx.x * 256 + threadIdx.x;   // 131072
    const int n0 = (gid & 31) * 4;
    const int p  = (gid >> 5) & 127;
    const int bh = gid >> 12;
    const int b = bh >> 3, h = bh & 7;
    const int blbase = b << 12;
    float4 carry = make_float4(0.f, 0.f, 0.f, 0.f);
#pragma unroll 4
    for (int c = 0; c < NCH; c++) {
        float* sp = g_S + ((size_t)(bh * NCH + c) * HEADDIM + p) * D_STATE + n0;
        float4 SL = *(float4*)sp;
        *(float4*)sp = carry;
        float Pt = g_cumP[(blbase + c * TCH + TCH - 1) * NHEADS + h];
        carry.x = SL.x + Pt * carry.x;
        carry.y = SL.y + Pt * carry.y;
        carry.z = SL.z + Pt * carry.z;
        carry.w = SL.w + Pt * carry.w;
    }
}

// =====================================================================
// ssd_inter (tensor core, 3xTF32): Y[t][p] += cumP_t * sum_n C_t[n]*S_in[p][n]
// One block per (c in 1..63, bh). A = cumP.C (64x128), B = S_in (128x128).
// hi/lo split on both operands; accumulate hi@hi + hi@lo + lo@hi.
// =====================================================================
#define IN_CHI 0
#define IN_CLO (64 * 132)
#define IN_SHI (2 * 64 * 132)
#define IN_SLO (2 * 64 * 132 + 128 * 132)
#define IN_WORDS (2 * 64 * 132 + 2 * 128 * 132)
#define INTER_SMEM_BYTES (IN_WORDS * 4)

__global__ __launch_bounds__(256) void ssd_inter_kernel() {
    extern __shared__ uint32_t sm[];
    uint32_t* Chi = sm + IN_CHI;
    uint32_t* Clo = sm + IN_CLO;
    uint32_t* Shi = sm + IN_SHI;
    uint32_t* Slo = sm + IN_SLO;

    const int tid = threadIdx.x;
    const int c  = blockIdx.x + 1;      // 1..63
    const int bh = blockIdx.y;
    const int b = bh >> 3, h = bh & 7;
    const int blbase = b << 12;
    const int t0g = blbase + c * TCH;
    const int wid = tid >> 5, lane = tid & 31;
    const int gid = lane >> 2, tig = lane & 3;

    // stage A = cumP_t * C_t, split hi/lo (64 rows x 128 n)
#pragma unroll
    for (int q = 0; q < 8; q++) {
        const int idx = q * 256 + tid;           // 0..2047
        const int j = idx >> 5, n4 = (idx & 31) * 4;
        const float cp = g_cumP[(t0g + j) * NHEADS + h];
        float4 cv = *(const float4*)(g_conv + (size_t)(t0g + j) * CONV_DIM
                                     + D_INNER + D_STATE + n4);
        cv.x *= cp; cv.y *= cp; cv.z *= cp; cv.w *= cp;
        uint4 uh, ul;
        uh.x = f2tf32(cv.x); ul.x = f2tf32(cv.x - __uint_as_float(uh.x));
        uh.y = f2tf32(cv.y); ul.y = f2tf32(cv.y - __uint_as_float(uh.y));
        uh.z = f2tf32(cv.z); ul.z = f2tf32(cv.z - __uint_as_float(uh.z));
        uh.w = f2tf32(cv.w); ul.w = f2tf32(cv.w - __uint_as_float(uh.w));
        *(uint4*)&Chi[j * 132 + n4] = uh;
        *(uint4*)&Clo[j * 132 + n4] = ul;
    }
    // stage B = S_in (128 p x 128 n), split hi/lo
    {
        const float* Sp = g_S + (size_t)(bh * NCH + c) * HEADDIM * D_STATE;
#pragma unroll
        for (int q = 0; q < 16; q++) {
            const int idx = q * 256 + tid;       // 0..4095
            const int p = idx >> 5, n4 = (idx & 31) * 4;
            float4 sv = *(const float4*)(Sp + (size_t)p * D_STATE + n4);
            uint4 uh, ul;
            uh.x = f2tf32(sv.x); ul.x = f2tf32(sv.x - __uint_as_float(uh.x));
            uh.y = f2tf32(sv.y); ul.y = f2tf32(sv.y - __uint_as_float(uh.y));
            uh.z = f2tf32(sv.z); ul.z = f2tf32(sv.z - __uint_as_float(uh.z));
            uh.w = f2tf32(sv.w); ul.w = f2tf32(sv.w - __uint_as_float(uh.w));
            *(uint4*)&Shi[p * 132 + n4] = uh;
            *(uint4*)&Slo[p * 132 + n4] = ul;
        }
    }
    __syncthreads();

    // warps: 2 (t) x 4 (p); warp tile 32t x 32p
    const int wt = (wid >> 2) * 32;
    const int wp = (wid & 3) * 32;
    float cY[2][4][4];
#pragma unroll
    for (int mi = 0; mi < 2; mi++)
#pragma unroll
        for (int ni = 0; ni < 4; ni++)
#pragma unroll
            for (int q = 0; q < 4; q++) cY[mi][ni][q] = 0.f;

#pragma unroll
    for (int kk = 0; kk < 128; kk += 8) {
        uint32_t ah[2][4], al[2][4], bh_[4][2], bl_[4][2];
#pragma unroll
        for (int mi = 0; mi < 2; mi++) {
            const int mr = wt + mi * 16 + gid;
            ah[mi][0] = Chi[mr * 132 + kk + tig];
            ah[mi][1] = Chi[(mr + 8) * 132 + kk + tig];
            ah[mi][2] = Chi[mr * 132 + kk + tig + 4];
            ah[mi][3] = Chi[(mr + 8) * 132 + kk + tig + 4];
            al[mi][0] = Clo[mr * 132 + kk + tig];
            al[mi][1] = Clo[(mr + 8) * 132 + kk + tig];
            al[mi][2] = Clo[mr * 132 + kk + tig + 4];
            al[mi][3] = Clo[(mr + 8) * 132 + kk + tig + 4];
        }
#pragma unroll
        for (int ni = 0; ni < 4; ni++) {
            const int nr = wp + ni * 8 + gid;
            bh_[ni][0] = Shi[nr * 132 + kk + tig];
            bh_[ni][1] = Shi[nr * 132 + kk + tig + 4];
            bl_[ni][0] = Slo[nr * 132 + kk + tig];
            bl_[ni][1] = Slo[nr * 132 + kk + tig + 4];
        }
#pragma unroll
        for (int mi = 0; mi < 2; mi++)
#pragma unroll
            for (int ni = 0; ni < 4; ni++) {
                MMA_TF32(cY[mi][ni], ah[mi], bh_[ni]);
                MMA_TF32(cY[mi][ni], ah[mi], bl_[ni]);
                MMA_TF32(cY[mi][ni], al[mi], bh_[ni]);
            }
    }

    // epilogue: RMW g_y
#pragma unroll
    for (int mi = 0; mi < 2; mi++) {
#pragma unroll
        for (int ni = 0; ni < 4; ni++) {
            const int p = wp + ni * 8 + tig * 2;
            const int r0 = t0g + wt + mi * 16 + gid, r1 = r0 + 8;
            float* y0 = g_y + (size_t)r0 * D_INNER + h * HEADDIM + p;
            float* y1 = g_y + (size_t)r1 * D_INNER + h * HEADDIM + p;
            float2 v0 = *(float2*)y0, v1 = *(float2*)y1;
            v0.x += cY[mi][ni][0]; v0.y += cY[mi][ni][1];
            v1.x += cY[mi][ni][2]; v1.y += cY[mi][ni][3];
            *(float2*)y0 = v0;
            *(float2*)y1 = v1;
        }
    }
}

// =====================================================================
// mulnorm: y = y * silu(z); y = y * rsqrt(mean(y^2)+1e-5) * norm_w
// =====================================================================
__global__ __launch_bounds__(256) void mulnorm_kernel(const float* __restrict__ norm_w) {
    __shared__ float red[8];
    __shared__ float rinv;
    const int bl = blockIdx.x, tid = threadIdx.x;
    const int lane = tid & 31, w = tid >> 5;
    float4 yv = *(const float4*)(g_y + (size_t)bl * D_INNER + tid * 4);
    float4 zv = *(const float4*)(g_zx + (size_t)bl * D_IN_PROJ + tid * 4);
    float4 t;
    t.x = yv.x * (zv.x / (1.f + expf(-zv.x)));
    t.y = yv.y * (zv.y / (1.f + expf(-zv.y)));
    t.z = yv.z * (zv.z / (1.f + expf(-zv.z)));
    t.w = yv.w * (zv.w / (1.f + expf(-zv.w)));
    float ss = t.x * t.x + t.y * t.y + t.z * t.z + t.w * t.w;
#pragma unroll
    for (int off = 16; off > 0; off >>= 1) ss += __shfl_xor_sync(0xffffffffu, ss, off);
    if (lane == 0) red[w] = ss;
    __syncthreads();
    if (tid == 0) {
        float tot = 0.f;
#pragma unroll
        for (int i = 0; i < 8; i++) tot += red[i];
        rinv = rsqrtf(tot * (1.f / (float)D_INNER) + 1e-5f);
    }
    __syncthreads();
    const float r = rinv;
    float4 w4 = *(const float4*)(norm_w + tid * 4);
    t.x *= r * w4.x; t.y *= r * w4.y; t.z *= r * w4.z; t.w *= r * w4.w;
    *(float4*)(g_y + (size_t)bl * D_INNER + tid * 4) = t;
}

// =====================================================================
// GEMM2 (tf32 tensor core): out[b][d][l] = sum_e Wo[d][e]*y[bl][e] + x.
// =====================================================================
__global__ __launch_bounds__(256) void gemm2_kernel(const float* __restrict__ Wo,
                                                    const float* __restrict__ x,
                                                    float* __restrict__ out) {
    __shared__ uint32_t As[128][20];   // [d][k]
    __shared__ uint32_t Bs[128][20];   // [l][k]
    const int tid = threadIdx.x;
    const int l0 = blockIdx.x * 128;
    const int d0 = blockIdx.y * 128;
    const int b  = blockIdx.z;
    const float* yp = g_y + (size_t)(b * LSEQ + l0) * D_INNER;

    const int rb = tid >> 1;           // 0..127
    const int kb = (tid & 1) * 8;      // 0 or 8

    const int wid = tid >> 5, lane = tid & 31;
    const int wm = (wid >> 2) * 64;
    const int wn = (wid & 3) * 32;
    const int gid = lane >> 2, tig = lane & 3;

    float c[4][4][4];
#pragma unroll
    for (int i = 0; i < 4; i++)
#pragma unroll
        for (int j = 0; j < 4; j++)
#pragma unroll
            for (int q = 0; q < 4; q++) c[i][j][q] = 0.f;

    for (int k0 = 0; k0 < D_INNER; k0 += 16) {
        float4 av0 = *(const float4*)(Wo + (size_t)(d0 + rb) * D_INNER + k0 + kb);
        float4 av1 = *(const float4*)(Wo + (size_t)(d0 + rb) * D_INNER + k0 + kb + 4);
        float4 bv0 = *(const float4*)(yp + (size_t)rb * D_INNER + k0 + kb);
        float4 bv1 = *(const float4*)(yp + (size_t)rb * D_INNER + k0 + kb + 4);
        __syncthreads();
        {
            uint4 t;
            t.x = f2tf32(av0.x); t.y = f2tf32(av0.y); t.z = f2tf32(av0.z); t.w = f2tf32(av0.w);
            *(uint4*)&As[rb][kb] = t;
            t.x = f2tf32(av1.x); t.y = f2tf32(av1.y); t.z = f2tf32(av1.z); t.w = f2tf32(av1.w);
            *(uint4*)&As[rb][kb + 4] = t;
            t.x = f2tf32(bv0.x); t.y = f2tf32(bv0.y); t.z = f2tf32(bv0.z); t.w = f2tf32(bv0.w);
            *(uint4*)&Bs[rb][kb] = t;
            t.x = f2tf32(bv1.x); t.y = f2tf32(bv1.y); t.z = f2tf32(bv1.z); t.w = f2tf32(bv1.w);
            *(uint4*)&Bs[rb][kb + 4] = t;
        }
        __syncthreads();
#pragma unroll
        for (int kk = 0; kk < 16; kk += 8) {
            uint32_t af[4][4], bf[4][2];
#pragma unroll
            for (int mi = 0; mi < 4; mi++) {
                const int mr = wm + mi * 16 + gid;
                af[mi][0] = As[mr][kk + tig];
                af[mi][1] = As[mr + 8][kk + tig];
                af[mi][2] = As[mr][kk + tig + 4];
                af[mi][3] = As[mr + 8][kk + tig + 4];
            }
#pragma unroll
            for (int ni = 0; ni < 4; ni++) {
                const int nr = wn + ni * 8 + gid;
                bf[ni][0] = Bs[nr][kk + tig];
                bf[ni][1] = Bs[nr][kk + tig + 4];
            }
#pragma unroll
            for (int mi = 0; mi < 4; mi++)
#pragma unroll
                for (int ni = 0; ni < 4; ni++)
                    MMA_TF32(c[mi][ni], af[mi], bf[ni]);
        }
    }

    const size_t base = (size_t)b * DIM * LSEQ;
#pragma unroll
    for (int mi = 0; mi < 4; mi++) {
#pragma unroll
        for (int ni = 0; ni < 4; ni++) {
            const int d = d0 + wm + mi * 16 + gid;
            const int l = l0 + wn + ni * 8 + tig * 2;
            const size_t off0 = base + (size_t)d * LSEQ + l;
            const size_t off1 = off0 + (size_t)8 * LSEQ;
            float2 x0 = *(const float2*)(x + off0);
            float2 x1 = *(const float2*)(x + off1);
            float2 o0; o0.x = c[mi][ni][0] + x0.x; o0.y = c[mi][ni][1] + x0.y;
            float2 o1; o1.x = c[mi][ni][2] + x1.x; o1.y = c[mi][ni][3] + x1.y;
            *(float2*)(out + off0) = o0;
            *(float2*)(out + off1) = o1;
        }
    }
}

// =====================================================================
extern "C" void kernel_launch(void* const* d_in, const int* in_sizes, int n_in,
                              void* d_out, int out_size) {
    const float* x          = (const float*)d_in[0];
    const float* in_proj_w  = (const float*)d_in[1];
    const float* conv_w     = (const float*)d_in[2];
    const float* conv_b     = (const float*)d_in[3];
    const float* dt_bias    = (const float*)d_in[4];
    const float* A_log      = (const float*)d_in[5];
    const float* D_param    = (const float*)d_in[6];
    const float* norm_w     = (const float*)d_in[7];
    const float* out_proj_w = (const float*)d_in[8];
    float* out = (float*)d_out;

    cudaFuncSetAttribute(ssd_intra_kernel,
                         cudaFuncAttributeMaxDynamicSharedMemorySize, SSD_SMEM_BYTES);
    cudaFuncSetAttribute(ssd_inter_kernel,
                         cudaFuncAttributeMaxDynamicSharedMemorySize, INTER_SMEM_BYTES);

    // 1. exact fp32 dt projection + softplus + dA
    dtprep_kernel<<<(NBL * NHEADS) / 256, 256>>>(x, in_proj_w, dt_bias, A_log);
    // 2. in_proj GEMM, tf32 tensor cores (cols 0..2303)
    gemm1_kernel<<<dim3(18, NBL / 128), 256>>>(x, in_proj_w);
    // 3. depthwise causal conv + SiLU
    conv_kernel<<<((size_t)NBL * CONV_DIM) / 256, 256>>>(conv_w, conv_b);
    // 4. SSD intra-chunk (tensor cores): Y_intra + chunk states
    ssd_intra_kernel<<<dim3(NCH, 32), 256, SSD_SMEM_BYTES>>>(A_log, D_param);
    // 5. within-chunk cumprod of dA
    cumP_kernel<<<256, 256>>>();
    // 6. chunk carry recurrence (pass B, 64 chunks)
    passB_kernel<<<(32 * HEADDIM * D_STATE / 4) / 256, 256>>>();
    // 7. inter-chunk Y via tensor cores (3xTF32, ~fp32 exact)
    ssd_inter_kernel<<<dim3(NCH - 1, 32), 256, INTER_SMEM_BYTES>>>();
    // 8. gate + RMSNorm
    mulnorm_kernel<<<NBL, 256>>>(norm_w);
    // 9. out_proj GEMM, tf32 tensor cores + residual, transposed store
    gemm2_kernel<<<dim3(LSEQ / 128, DIM / 128, BSZ), 256>>>(out_proj_w, x, out);
}